// round 3
// baseline (speedup 1.0000x reference)
#include <cuda_runtime.h>
#include <cstdint>

#define NMAX   100352          // >= N = 100000
#define CIN    128

// -------- scratch (no allocations allowed) --------
__device__ float              g_sj[NMAX * 4];      // s_j[n][h]
__device__ float              g_si[NMAX * 4];      // s_i[n][h]
__device__ unsigned long long g_best[NMAX * 4];    // per (src, head): packed (ordf(alpha)<<32)|(0xFFFFFFFF-e)
__device__ float              g_maskf[NMAX];       // node_mask as float 0/1

// orderable-uint mapping for float (monotone)
__device__ __forceinline__ unsigned ordf(float f) {
    unsigned u = __float_as_uint(f);
    return (u & 0x80000000u) ? ~u : (u | 0x80000000u);
}
__device__ __forceinline__ unsigned long long make_key(float a, unsigned e) {
    return ((unsigned long long)ordf(a) << 32) | (unsigned long long)(0xFFFFFFFFu - e);
}

// -------- K1: zero scratch + fold V (per-block shared) + s = x @ V --------
__global__ __launch_bounds__(256) void k_scores(const float* __restrict__ x,
                                                const float* __restrict__ weight,
                                                const float* __restrict__ att,
                                                int N) {
    int t   = blockIdx.x * blockDim.x + threadIdx.x;
    int gsz = gridDim.x * blockDim.x;

    // zero best table + mask (must complete before k_argmax / k_winner; kernel
    // boundary provides the ordering)
    for (int i = t; i < N * 4; i += gsz) g_best[i] = 0ull;
    for (int i = t; i < N;     i += gsz) g_maskf[i] = 0.0f;

    // fold weight (128x128) + att (4x64) into V (128x8) in shared.
    // o = 0..3 -> s_j heads, 4..7 -> s_i heads. weight is tiny & L2-hot.
    __shared__ float sV[CIN * 8];
    {
        int tt = threadIdx.x;
        #pragma unroll
        for (int r = 0; r < 4; r++) {
            int idx = tt * 4 + r;          // [0,1024)
            int k = idx >> 3, o = idx & 7, h = o & 3;
            int ba = h * 64 + ((o >= 4) ? 32 : 0);
            const float* wrow = weight + k * CIN + h * 32;
            float s = 0.f;
            #pragma unroll
            for (int c = 0; c < 32; c++) s += wrow[c] * att[ba + c];
            sV[idx] = s;
        }
    }
    __syncthreads();

    int lane   = threadIdx.x & 31;
    int warpId = t >> 5;
    int nW     = gsz >> 5;

    // each lane owns 4 rows of V (rows lane*4 .. lane*4+3), 8 cols each
    float4 Vj[4], Vi[4];
    #pragma unroll
    for (int r = 0; r < 4; r++) {
        const float4* vp = (const float4*)(sV + (lane * 4 + r) * 8);
        Vj[r] = vp[0];
        Vi[r] = vp[1];
    }

    const float4* x4 = (const float4*)x;
    // two nodes in flight per iteration for MLP
    for (int n0 = warpId; n0 < N; n0 += 2 * nW) {
        int  n1   = n0 + nW;
        bool has1 = (n1 < N);
        float4 xa = __ldcs(&x4[(size_t)n0 * 32 + lane]);
        float4 xb = has1 ? __ldcs(&x4[(size_t)n1 * 32 + lane])
                         : make_float4(0.f, 0.f, 0.f, 0.f);

        float accA[8], accB[8];
        #pragma unroll
        for (int o = 0; o < 8; o++) {
            const float4* V0 = (o < 4) ? Vj : Vi;
            int oo = o & 3;
            float v0 = (oo == 0) ? V0[0].x : (oo == 1) ? V0[0].y : (oo == 2) ? V0[0].z : V0[0].w;
            float v1 = (oo == 0) ? V0[1].x : (oo == 1) ? V0[1].y : (oo == 2) ? V0[1].z : V0[1].w;
            float v2 = (oo == 0) ? V0[2].x : (oo == 1) ? V0[2].y : (oo == 2) ? V0[2].z : V0[2].w;
            float v3 = (oo == 0) ? V0[3].x : (oo == 1) ? V0[3].y : (oo == 2) ? V0[3].z : V0[3].w;
            accA[o] = xa.x * v0 + xa.y * v1 + xa.z * v2 + xa.w * v3;
            accB[o] = xb.x * v0 + xb.y * v1 + xb.z * v2 + xb.w * v3;
        }
        #pragma unroll
        for (int off = 16; off > 0; off >>= 1) {
            #pragma unroll
            for (int o = 0; o < 8; o++) {
                accA[o] += __shfl_xor_sync(0xFFFFFFFFu, accA[o], off);
                accB[o] += __shfl_xor_sync(0xFFFFFFFFu, accB[o], off);
            }
        }
        if (lane == 0) {
            ((float4*)g_sj)[n0] = make_float4(accA[0], accA[1], accA[2], accA[3]);
            ((float4*)g_si)[n0] = make_float4(accA[4], accA[5], accA[6], accA[7]);
            if (has1) {
                ((float4*)g_sj)[n1] = make_float4(accB[0], accB[1], accB[2], accB[3]);
                ((float4*)g_si)[n1] = make_float4(accB[4], accB[5], accB[6], accB[7]);
            }
        }
    }
}

// -------- K2: per-edge argmax via read-before-atomic --------
__global__ __launch_bounds__(256) void k_argmax(const int* __restrict__ srcp,
                                                const int* __restrict__ dstp, int E) {
    int e = blockIdx.x * blockDim.x + threadIdx.x;
    if (e >= E) return;
    int s = srcp[e], d = dstp[e];
    float4 sj = ((const float4*)g_sj)[s];
    float4 si = ((const float4*)g_si)[d];
    unsigned long long k0 = make_key(sj.x + si.x, (unsigned)e);
    unsigned long long k1 = make_key(sj.y + si.y, (unsigned)e);
    unsigned long long k2 = make_key(sj.z + si.z, (unsigned)e);
    unsigned long long k3 = make_key(sj.w + si.w, (unsigned)e);
    unsigned long long* b = g_best + (size_t)s * 4;
    ulonglong2 p0 = *(const ulonglong2*)b;
    ulonglong2 p1 = *((const ulonglong2*)b + 1);
    // read-before-atomic: possibly-stale read only causes an extra (harmless) atomic
    if (k0 > p0.x) atomicMax(&b[0], k0);
    if (k1 > p0.y) atomicMax(&b[1], k1);
    if (k2 > p1.x) atomicMax(&b[2], k2);
    if (k3 > p1.y) atomicMax(&b[3], k3);
}

// -------- K3: winner decode -> mark dst; fused streaming zero-fill of x_out --------
__global__ __launch_bounds__(256) void k_winner(const int* __restrict__ dstp,
                                                float4* __restrict__ out_zero,
                                                int zero_n4, int N) {
    int t   = blockIdx.x * blockDim.x + threadIdx.x;
    int gsz = gridDim.x * blockDim.x;

    if (t < N * 4) {
        unsigned long long key = g_best[t];
        if (key != 0ull) {
            unsigned e = 0xFFFFFFFFu - (unsigned)key;   // low 32 bits = 0xFFFFFFFF - e
            g_maskf[dstp[e]] = 1.0f;                    // benign race: all write 1.0
        }
    }
    // streaming (evict-first) zeros: overlaps the latency-bound phase above and
    // does NOT evict srcp/dstp/maskf from L2 (k_out reuses them next)
    float4 z = make_float4(0.f, 0.f, 0.f, 0.f);
    for (int i = t; i < zero_n4; i += gsz) __stcs(&out_zero[i], z);
}

// -------- K4: edge_keep, node_mask floats, batch slices --------
__global__ __launch_bounds__(256) void k_out(const int* __restrict__ srcp,
                                             const int* __restrict__ dstp,
                                             const int* __restrict__ slices,
                                             float* __restrict__ out_keep,
                                             float* __restrict__ out_mask,
                                             float* __restrict__ out_slices,
                                             int E, int N) {
    int i = blockIdx.x * blockDim.x + threadIdx.x;
    if (i < E) {
        out_keep[i] = g_maskf[srcp[i]] * g_maskf[dstp[i]];   // AND of {0,1} floats
    }
    if (i < N) out_mask[i] = g_maskf[i];
    if (i == 0) {
        out_slices[0] = (float)slices[0];
        out_slices[1] = (float)slices[1];
    }
}

extern "C" void kernel_launch(void* const* d_in, const int* in_sizes, int n_in,
                              void* d_out, int out_size) {
    const float* x      = (const float*)d_in[0];
    const int*   eidx   = (const int*)d_in[1];
    const int*   slices = (const int*)d_in[2];
    const float* weight = (const float*)d_in[3];
    const float* att    = (const float*)d_in[4];

    int N = in_sizes[0] / CIN;
    int E = in_sizes[1] / 2;
    const int* srcp = eidx;
    const int* dstp = eidx + E;

    float* out = (float*)d_out;
    size_t xout_elems = (size_t)N * CIN;

    if ((size_t)out_size < xout_elems + (size_t)E + (size_t)N + 2) {
        cudaMemsetAsync(out, 0, (size_t)out_size * sizeof(float), 0);
        return;
    }

    float* out_keep   = out + xout_elems;
    float* out_mask   = out_keep + E;
    float* out_slices = out_mask + N;

    int zero_n4 = (int)(xout_elems / 4);            // CIN=128 -> divisible by 4

    k_scores<<<1184, 256>>>(x, weight, att, N);     // 8 blocks/SM persistent-ish
    k_argmax<<<(E + 255) / 256, 256>>>(srcp, dstp, E);
    k_winner<<<(N * 4 + 255) / 256, 256>>>(dstp, (float4*)out, zero_n4, N);
    int m = (E > N) ? E : N;
    k_out<<<(m + 255) / 256, 256>>>(srcp, dstp, slices, out_keep, out_mask, out_slices, E, N);
}

// round 6
// speedup vs baseline: 1.5853x; 1.5853x over previous
#include <cuda_runtime.h>
#include <cstdint>

#define NMAX   100352          // >= N = 100000
#define CIN    128

// -------- scratch (no allocations allowed) --------
__device__ float              g_V[CIN * 8];        // folded weight: [k][o], o=0..3 -> s_j heads, 4..7 -> s_i heads
__device__ float              g_sj[NMAX * 4];      // s_j[n][h]
__device__ float              g_si[NMAX * 4];      // s_i[n][h]
__device__ unsigned long long g_best[NMAX * 4];    // per (src, head): packed (ordf(alpha)<<32)|(0xFFFFFFFF-e)
__device__ float              g_maskf[NMAX];       // node_mask as float 0/1

// orderable-uint mapping for float (monotone)
__device__ __forceinline__ unsigned ordf(float f) {
    unsigned u = __float_as_uint(f);
    return (u & 0x80000000u) ? ~u : (u | 0x80000000u);
}
__device__ __forceinline__ unsigned long long make_key(float a, unsigned e) {
    return ((unsigned long long)ordf(a) << 32) | (unsigned long long)(0xFFFFFFFFu - e);
}

// -------- K1: zero best table + mask, fold weights into V (128x8) --------
__global__ __launch_bounds__(256) void k_init(const float* __restrict__ weight,
                                              const float* __restrict__ att, int N) {
    int i = blockIdx.x * blockDim.x + threadIdx.x;
    int tot = N * 4;
    if (i < tot) g_best[i] = 0ull;
    if (i < N)   g_maskf[i] = 0.0f;
    if (i < 1024) {
        int k = i >> 3;                // row of weight
        int o = i & 7;                 // 0..3 = s_j heads, 4..7 = s_i heads
        int h = o & 3;
        int base_att = h * 64 + ((o >= 4) ? 32 : 0);
        const float* wrow = weight + k * CIN + h * 32;
        float s = 0.f;
        #pragma unroll
        for (int c = 0; c < 32; c++) s += wrow[c] * att[base_att + c];
        g_V[k * 8 + o] = s;
    }
}

// -------- K2: s = x @ V (one warp/node, shuffle-reduce) + fused streaming zero-fill --------
// The zero-fill of x_out rides on this kernel's spare store bandwidth: k_scores is
// shuffle/compute bound on its 51MB read; fire-and-forget __stcs writes cost issue
// slots only and stream past L2 (evict-first) so they don't pollute anything.
__global__ __launch_bounds__(256) void k_scores(const float* __restrict__ x,
                                                float4* __restrict__ out_zero,
                                                int zero_n4, int N) {
    int t   = blockIdx.x * blockDim.x + threadIdx.x;
    int gsz = gridDim.x * blockDim.x;

    float4 z = make_float4(0.f, 0.f, 0.f, 0.f);
    for (int i = t; i < zero_n4; i += gsz) __stcs(&out_zero[i], z);

    int lane   = threadIdx.x & 31;
    int warpId = t >> 5;
    int nWarps = gsz >> 5;

    // each lane owns 4 rows of V (rows lane*4 .. lane*4+3), 8 cols each
    float4 Vj[4], Vi[4];
    #pragma unroll
    for (int r = 0; r < 4; r++) {
        const float4* vp = (const float4*)(g_V + (lane * 4 + r) * 8);
        Vj[r] = vp[0];
        Vi[r] = vp[1];
    }

    const float4* x4 = (const float4*)x;
    for (int n = warpId; n < N; n += nWarps) {
        float4 xv = x4[(size_t)n * 32 + lane];
        float acc[8];
        acc[0] = xv.x * Vj[0].x + xv.y * Vj[1].x + xv.z * Vj[2].x + xv.w * Vj[3].x;
        acc[1] = xv.x * Vj[0].y + xv.y * Vj[1].y + xv.z * Vj[2].y + xv.w * Vj[3].y;
        acc[2] = xv.x * Vj[0].z + xv.y * Vj[1].z + xv.z * Vj[2].z + xv.w * Vj[3].z;
        acc[3] = xv.x * Vj[0].w + xv.y * Vj[1].w + xv.z * Vj[2].w + xv.w * Vj[3].w;
        acc[4] = xv.x * Vi[0].x + xv.y * Vi[1].x + xv.z * Vi[2].x + xv.w * Vi[3].x;
        acc[5] = xv.x * Vi[0].y + xv.y * Vi[1].y + xv.z * Vi[2].y + xv.w * Vi[3].y;
        acc[6] = xv.x * Vi[0].z + xv.y * Vi[1].z + xv.z * Vi[2].z + xv.w * Vi[3].z;
        acc[7] = xv.x * Vi[0].w + xv.y * Vi[1].w + xv.z * Vi[2].w + xv.w * Vi[3].w;
        #pragma unroll
        for (int off = 16; off > 0; off >>= 1) {
            #pragma unroll
            for (int o = 0; o < 8; o++)
                acc[o] += __shfl_xor_sync(0xFFFFFFFFu, acc[o], off);
        }
        if (lane == 0) {
            ((float4*)g_sj)[n] = make_float4(acc[0], acc[1], acc[2], acc[3]);
            ((float4*)g_si)[n] = make_float4(acc[4], acc[5], acc[6], acc[7]);
        }
    }
}

// -------- argmax core: read-before-atomic on packed keys --------
__device__ __forceinline__ void argmax_edge(int e, int s, int d) {
    float4 sj = ((const float4*)g_sj)[s];
    float4 si = ((const float4*)g_si)[d];
    unsigned long long k0 = make_key(sj.x + si.x, (unsigned)e);
    unsigned long long k1 = make_key(sj.y + si.y, (unsigned)e);
    unsigned long long k2 = make_key(sj.z + si.z, (unsigned)e);
    unsigned long long k3 = make_key(sj.w + si.w, (unsigned)e);
    unsigned long long* b = g_best + (size_t)s * 4;
    ulonglong2 p0 = *(const ulonglong2*)b;
    ulonglong2 p1 = *((const ulonglong2*)b + 1);
    // possibly-stale read only causes an extra (harmless) atomic
    if (k0 > p0.x) atomicMax(&b[0], k0);
    if (k1 > p0.y) atomicMax(&b[1], k1);
    if (k2 > p1.x) atomicMax(&b[2], k2);
    if (k3 > p1.y) atomicMax(&b[3], k3);
}

// -------- K3: per-edge argmax, 4 edges/thread via int4 (E % 4 == 0 path) --------
__global__ __launch_bounds__(256) void k_argmax_v4(const int* __restrict__ srcp,
                                                   const int* __restrict__ dstp, int E) {
    int e4 = (blockIdx.x * blockDim.x + threadIdx.x) * 4;
    if (e4 >= E) return;
    int4 s4 = *(const int4*)(srcp + e4);
    int4 d4 = *(const int4*)(dstp + e4);
    argmax_edge(e4 + 0, s4.x, d4.x);
    argmax_edge(e4 + 1, s4.y, d4.y);
    argmax_edge(e4 + 2, s4.z, d4.z);
    argmax_edge(e4 + 3, s4.w, d4.w);
}

__global__ __launch_bounds__(256) void k_argmax_s(const int* __restrict__ srcp,
                                                  const int* __restrict__ dstp, int E) {
    int e = blockIdx.x * blockDim.x + threadIdx.x;
    if (e >= E) return;
    argmax_edge(e, srcp[e], dstp[e]);
}

// -------- K4: node-parallel winner decode -> mark dst of winning edge --------
__global__ __launch_bounds__(256) void k_winner(const int* __restrict__ dstp, int N) {
    int i = blockIdx.x * blockDim.x + threadIdx.x;
    if (i >= N * 4) return;
    unsigned long long key = g_best[i];
    if (key != 0ull) {
        unsigned e = 0xFFFFFFFFu - (unsigned)key;   // low 32 bits = 0xFFFFFFFF - e
        g_maskf[dstp[e]] = 1.0f;                    // benign race: all write 1.0
    }
}

// -------- K5: edge_keep + node_mask + slices, 4 elements/thread --------
__global__ __launch_bounds__(256) void k_out_v4(const int* __restrict__ srcp,
                                                const int* __restrict__ dstp,
                                                const int* __restrict__ slices,
                                                float* __restrict__ out_keep,
                                                float* __restrict__ out_mask,
                                                float* __restrict__ out_slices,
                                                int E, int N) {
    int t  = blockIdx.x * blockDim.x + threadIdx.x;
    int i4 = t * 4;
    if (i4 < E) {
        int4 s4 = *(const int4*)(srcp + i4);
        int4 d4 = *(const int4*)(dstp + i4);
        float4 r;
        r.x = g_maskf[s4.x] * g_maskf[d4.x];
        r.y = g_maskf[s4.y] * g_maskf[d4.y];
        r.z = g_maskf[s4.z] * g_maskf[d4.z];
        r.w = g_maskf[s4.w] * g_maskf[d4.w];
        *(float4*)(out_keep + i4) = r;
    }
    if (i4 < N) {
        float4 m;
        m.x = g_maskf[i4 + 0];
        m.y = (i4 + 1 < N) ? g_maskf[i4 + 1] : 0.f;
        m.z = (i4 + 2 < N) ? g_maskf[i4 + 2] : 0.f;
        m.w = (i4 + 3 < N) ? g_maskf[i4 + 3] : 0.f;
        if (i4 + 3 < N) *(float4*)(out_mask + i4) = m;
        else {
            out_mask[i4] = m.x;
            if (i4 + 1 < N) out_mask[i4 + 1] = m.y;
            if (i4 + 2 < N) out_mask[i4 + 2] = m.z;
        }
    }
    if (t == 0) {
        out_slices[0] = (float)slices[0];
        out_slices[1] = (float)slices[1];
    }
}

__global__ __launch_bounds__(256) void k_out_s(const int* __restrict__ srcp,
                                               const int* __restrict__ dstp,
                                               const int* __restrict__ slices,
                                               float* __restrict__ out_keep,
                                               float* __restrict__ out_mask,
                                               float* __restrict__ out_slices,
                                               int E, int N) {
    int i = blockIdx.x * blockDim.x + threadIdx.x;
    if (i < E) out_keep[i] = g_maskf[srcp[i]] * g_maskf[dstp[i]];
    if (i < N) out_mask[i] = g_maskf[i];
    if (i == 0) {
        out_slices[0] = (float)slices[0];
        out_slices[1] = (float)slices[1];
    }
}

extern "C" void kernel_launch(void* const* d_in, const int* in_sizes, int n_in,
                              void* d_out, int out_size) {
    const float* x      = (const float*)d_in[0];
    const int*   eidx   = (const int*)d_in[1];
    const int*   slices = (const int*)d_in[2];
    const float* weight = (const float*)d_in[3];
    const float* att    = (const float*)d_in[4];

    int N = in_sizes[0] / CIN;
    int E = in_sizes[1] / 2;
    const int* srcp = eidx;
    const int* dstp = eidx + E;

    float* out = (float*)d_out;
    size_t xout_elems = (size_t)N * CIN;

    if ((size_t)out_size < xout_elems + (size_t)E + (size_t)N + 2) {
        cudaMemsetAsync(out, 0, (size_t)out_size * sizeof(float), 0);
        return;
    }

    float* out_keep   = out + xout_elems;
    float* out_mask   = out_keep + E;
    float* out_slices = out_mask + N;

    int zero_n4 = (int)(xout_elems / 4);            // CIN=128 -> divisible by 4
    bool vec_ok = ((E & 3) == 0);                   // int4 alignment of dstp/out_keep

    k_init<<<(N * 4 + 255) / 256, 256>>>(weight, att, N);
    k_scores<<<832, 256>>>(x, (float4*)out, zero_n4, N);

    if (vec_ok) k_argmax_v4<<<(E / 4 + 255) / 256, 256>>>(srcp, dstp, E);
    else        k_argmax_s<<<(E + 255) / 256, 256>>>(srcp, dstp, E);

    k_winner<<<(N * 4 + 255) / 256, 256>>>(dstp, N);

    if (vec_ok) {
        int m4 = ((E > N ? E : N) + 3) / 4;
        k_out_v4<<<(m4 + 255) / 256, 256>>>(srcp, dstp, slices, out_keep, out_mask, out_slices, E, N);
    } else {
        int m = (E > N) ? E : N;
        k_out_s<<<(m + 255) / 256, 256>>>(srcp, dstp, slices, out_keep, out_mask, out_slices, E, N);
    }
}

// round 8
// speedup vs baseline: 2.0008x; 1.2621x over previous
#include <cuda_runtime.h>
#include <cstdint>

#define NMAX   100352          // >= N = 100000
#define CIN    128

// -------- scratch (no allocations allowed) --------
// NOTE: s_j is gone. alpha(e) = s_j[src] + s_i[dst]; per-src argmax is invariant
// under the constant s_j[src] offset (float add of a constant is monotone, and
// exact si-ties are exact alpha-ties, broken identically by min edge id).
__device__ float              g_Vi[CIN * 4];       // folded weight for s_i: [k][h]
__device__ float              g_si[NMAX * 4];      // s_i[n][h]
__device__ unsigned long long g_best[NMAX * 4];    // per (src, head): packed (ordf(si)<<32)|(0xFFFFFFFF-e)
__device__ float              g_maskf[NMAX];       // node_mask as float 0/1

// orderable-uint mapping for float (monotone)
__device__ __forceinline__ unsigned ordf(float f) {
    unsigned u = __float_as_uint(f);
    return (u & 0x80000000u) ? ~u : (u | 0x80000000u);
}
__device__ __forceinline__ unsigned long long make_key(float a, unsigned e) {
    return ((unsigned long long)ordf(a) << 32) | (unsigned long long)(0xFFFFFFFFu - e);
}

// -------- K1: zero best table + mask, fold weight+att into Vi (128x4) --------
__global__ __launch_bounds__(256) void k_init(const float* __restrict__ weight,
                                              const float* __restrict__ att, int N) {
    int i = blockIdx.x * blockDim.x + threadIdx.x;
    int tot = N * 4;
    if (i < tot) g_best[i] = 0ull;
    if (i < N)   g_maskf[i] = 0.0f;
    if (i < 512) {
        int k = i >> 2;                // row of weight
        int h = i & 3;                 // head
        int base_att = h * 64 + 32;    // w_i half of att_weight
        const float* wrow = weight + k * CIN + h * 32;
        float s = 0.f;
        #pragma unroll
        for (int c = 0; c < 32; c++) s += wrow[c] * att[base_att + c];
        g_Vi[k * 4 + h] = s;
    }
}

// -------- K2: s_i = x @ Vi (one warp/node, shuffle-reduce) + fused streaming zero-fill --------
__global__ __launch_bounds__(256) void k_scores(const float* __restrict__ x,
                                                float4* __restrict__ out_zero,
                                                int zero_n4, int N) {
    int t   = blockIdx.x * blockDim.x + threadIdx.x;
    int gsz = gridDim.x * blockDim.x;

    float4 z = make_float4(0.f, 0.f, 0.f, 0.f);
    for (int i = t; i < zero_n4; i += gsz) __stcs(&out_zero[i], z);

    int lane   = threadIdx.x & 31;
    int warpId = t >> 5;
    int nWarps = gsz >> 5;

    // each lane owns 4 rows of Vi (rows lane*4 .. lane*4+3), 4 cols each
    float4 Vi[4];
    #pragma unroll
    for (int r = 0; r < 4; r++)
        Vi[r] = ((const float4*)g_Vi)[lane * 4 + r];

    const float4* x4 = (const float4*)x;
    for (int n = warpId; n < N; n += nWarps) {
        float4 xv = x4[(size_t)n * 32 + lane];
        float acc[4];
        acc[0] = xv.x * Vi[0].x + xv.y * Vi[1].x + xv.z * Vi[2].x + xv.w * Vi[3].x;
        acc[1] = xv.x * Vi[0].y + xv.y * Vi[1].y + xv.z * Vi[2].y + xv.w * Vi[3].y;
        acc[2] = xv.x * Vi[0].z + xv.y * Vi[1].z + xv.z * Vi[2].z + xv.w * Vi[3].z;
        acc[3] = xv.x * Vi[0].w + xv.y * Vi[1].w + xv.z * Vi[2].w + xv.w * Vi[3].w;
        #pragma unroll
        for (int off = 16; off > 0; off >>= 1) {
            #pragma unroll
            for (int o = 0; o < 4; o++)
                acc[o] += __shfl_xor_sync(0xFFFFFFFFu, acc[o], off);
        }
        if (lane == 0)
            ((float4*)g_si)[n] = make_float4(acc[0], acc[1], acc[2], acc[3]);
    }
}

// -------- argmax core: ONE gather (si[d]) + read-before-atomic on packed keys --------
__device__ __forceinline__ void argmax_edge(int e, int s, int d) {
    float4 si = ((const float4*)g_si)[d];
    unsigned long long k0 = make_key(si.x, (unsigned)e);
    unsigned long long k1 = make_key(si.y, (unsigned)e);
    unsigned long long k2 = make_key(si.z, (unsigned)e);
    unsigned long long k3 = make_key(si.w, (unsigned)e);
    unsigned long long* b = g_best + (size_t)s * 4;
    ulonglong2 p0 = *(const ulonglong2*)b;
    ulonglong2 p1 = *((const ulonglong2*)b + 1);
    // possibly-stale read only causes an extra (harmless) atomic
    if (k0 > p0.x) atomicMax(&b[0], k0);
    if (k1 > p0.y) atomicMax(&b[1], k1);
    if (k2 > p1.x) atomicMax(&b[2], k2);
    if (k3 > p1.y) atomicMax(&b[3], k3);
}

// -------- K3: per-edge argmax, 4 edges/thread via int4 (E % 4 == 0 path) --------
__global__ __launch_bounds__(256) void k_argmax_v4(const int* __restrict__ srcp,
                                                   const int* __restrict__ dstp, int E) {
    int e4 = (blockIdx.x * blockDim.x + threadIdx.x) * 4;
    if (e4 >= E) return;
    int4 s4 = *(const int4*)(srcp + e4);
    int4 d4 = *(const int4*)(dstp + e4);
    argmax_edge(e4 + 0, s4.x, d4.x);
    argmax_edge(e4 + 1, s4.y, d4.y);
    argmax_edge(e4 + 2, s4.z, d4.z);
    argmax_edge(e4 + 3, s4.w, d4.w);
}

__global__ __launch_bounds__(256) void k_argmax_s(const int* __restrict__ srcp,
                                                  const int* __restrict__ dstp, int E) {
    int e = blockIdx.x * blockDim.x + threadIdx.x;
    if (e >= E) return;
    argmax_edge(e, srcp[e], dstp[e]);
}

// -------- K4: node-parallel winner decode -> mark dst of winning edge --------
__global__ __launch_bounds__(256) void k_winner(const int* __restrict__ dstp, int N) {
    int i = blockIdx.x * blockDim.x + threadIdx.x;
    if (i >= N * 4) return;
    unsigned long long key = g_best[i];
    if (key != 0ull) {
        unsigned e = 0xFFFFFFFFu - (unsigned)key;   // low 32 bits = 0xFFFFFFFF - e
        g_maskf[dstp[e]] = 1.0f;                    // benign race: all write 1.0
    }
}

// -------- K5: edge_keep + node_mask + slices, 4 elements/thread --------
__global__ __launch_bounds__(256) void k_out_v4(const int* __restrict__ srcp,
                                                const int* __restrict__ dstp,
                                                const int* __restrict__ slices,
                                                float* __restrict__ out_keep,
                                                float* __restrict__ out_mask,
                                                float* __restrict__ out_slices,
                                                int E, int N) {
    int t  = blockIdx.x * blockDim.x + threadIdx.x;
    int i4 = t * 4;
    if (i4 < E) {
        int4 s4 = *(const int4*)(srcp + i4);
        int4 d4 = *(const int4*)(dstp + i4);
        float4 r;
        r.x = g_maskf[s4.x] * g_maskf[d4.x];
        r.y = g_maskf[s4.y] * g_maskf[d4.y];
        r.z = g_maskf[s4.z] * g_maskf[d4.z];
        r.w = g_maskf[s4.w] * g_maskf[d4.w];
        *(float4*)(out_keep + i4) = r;
    }
    if (i4 < N) {
        float4 m;
        m.x = g_maskf[i4 + 0];
        m.y = (i4 + 1 < N) ? g_maskf[i4 + 1] : 0.f;
        m.z = (i4 + 2 < N) ? g_maskf[i4 + 2] : 0.f;
        m.w = (i4 + 3 < N) ? g_maskf[i4 + 3] : 0.f;
        if (i4 + 3 < N) *(float4*)(out_mask + i4) = m;
        else {
            out_mask[i4] = m.x;
            if (i4 + 1 < N) out_mask[i4 + 1] = m.y;
            if (i4 + 2 < N) out_mask[i4 + 2] = m.z;
        }
    }
    if (t == 0) {
        out_slices[0] = (float)slices[0];
        out_slices[1] = (float)slices[1];
    }
}

__global__ __launch_bounds__(256) void k_out_s(const int* __restrict__ srcp,
                                               const int* __restrict__ dstp,
                                               const int* __restrict__ slices,
                                               float* __restrict__ out_keep,
                                               float* __restrict__ out_mask,
                                               float* __restrict__ out_slices,
                                               int E, int N) {
    int i = blockIdx.x * blockDim.x + threadIdx.x;
    if (i < E) out_keep[i] = g_maskf[srcp[i]] * g_maskf[dstp[i]];
    if (i < N) out_mask[i] = g_maskf[i];
    if (i == 0) {
        out_slices[0] = (float)slices[0];
        out_slices[1] = (float)slices[1];
    }
}

extern "C" void kernel_launch(void* const* d_in, const int* in_sizes, int n_in,
                              void* d_out, int out_size) {
    const float* x      = (const float*)d_in[0];
    const int*   eidx   = (const int*)d_in[1];
    const int*   slices = (const int*)d_in[2];
    const float* weight = (const float*)d_in[3];
    const float* att    = (const float*)d_in[4];

    int N = in_sizes[0] / CIN;
    int E = in_sizes[1] / 2;
    const int* srcp = eidx;
    const int* dstp = eidx + E;

    float* out = (float*)d_out;
    size_t xout_elems = (size_t)N * CIN;

    if ((size_t)out_size < xout_elems + (size_t)E + (size_t)N + 2) {
        cudaMemsetAsync(out, 0, (size_t)out_size * sizeof(float), 0);
        return;
    }

    float* out_keep   = out + xout_elems;
    float* out_mask   = out_keep + E;
    float* out_slices = out_mask + N;

    int zero_n4 = (int)(xout_elems / 4);            // CIN=128 -> divisible by 4
    bool vec_ok = ((E & 3) == 0);                   // int4 alignment of dstp/out_keep

    k_init<<<(N * 4 + 255) / 256, 256>>>(weight, att, N);
    k_scores<<<832, 256>>>(x, (float4*)out, zero_n4, N);

    if (vec_ok) k_argmax_v4<<<(E / 4 + 255) / 256, 256>>>(srcp, dstp, E);
    else        k_argmax_s<<<(E + 255) / 256, 256>>>(srcp, dstp, E);

    k_winner<<<(N * 4 + 255) / 256, 256>>>(dstp, N);

    if (vec_ok) {
        int m4 = ((E > N ? E : N) + 3) / 4;
        k_out_v4<<<(m4 + 255) / 256, 256>>>(srcp, dstp, slices, out_keep, out_mask, out_slices, E, N);
    } else {
        int m = (E > N) ? E : N;
        k_out_s<<<(m + 255) / 256, 256>>>(srcp, dstp, slices, out_keep, out_mask, out_slices, E, N);
    }
}

// round 9
// speedup vs baseline: 2.0991x; 1.0491x over previous
#include <cuda_runtime.h>
#include <cstdint>

#define NMAX   100352          // >= N = 100000
#define CIN    128

// -------- scratch (no allocations allowed) --------
// alpha(e) = s_j[src] + s_i[dst]; per-src argmax is invariant under the constant
// s_j[src] offset (float add of a constant is monotone; exact si-ties are exact
// alpha-ties, broken identically by min edge id). So only s_i exists.
__device__ float              g_Vi[CIN * 4];       // folded weight for s_i: [k][h]
__device__ float              g_si[NMAX * 4];      // s_i[n][h]
__device__ unsigned long long g_best[NMAX * 4];    // per (src, head): packed (ordf(si)<<32)|(0xFFFFFFFF-e)
__device__ float              g_maskf[NMAX];       // node_mask as float 0/1

// orderable-uint mapping for float (monotone)
__device__ __forceinline__ unsigned ordf(float f) {
    unsigned u = __float_as_uint(f);
    return (u & 0x80000000u) ? ~u : (u | 0x80000000u);
}
__device__ __forceinline__ unsigned long long make_key(float a, unsigned e) {
    return ((unsigned long long)ordf(a) << 32) | (unsigned long long)(0xFFFFFFFFu - e);
}

// -------- K1: zero best table + mask, fold weight+att into Vi (128x4) --------
__global__ __launch_bounds__(256) void k_init(const float* __restrict__ weight,
                                              const float* __restrict__ att, int N) {
    int i = blockIdx.x * blockDim.x + threadIdx.x;
    int tot = N * 4;
    if (i < tot) g_best[i] = 0ull;
    if (i < N)   g_maskf[i] = 0.0f;
    if (i < 512) {
        int k = i >> 2;                // row of weight
        int h = i & 3;                 // head
        int base_att = h * 64 + 32;    // w_i half of att_weight
        const float* wrow = weight + k * CIN + h * 32;
        float s = 0.f;
        #pragma unroll
        for (int c = 0; c < 32; c++) s += wrow[c] * att[base_att + c];
        g_Vi[k * 4 + h] = s;
    }
}

// -------- K2: s_i = x @ Vi (one warp/node, shuffle-reduce) + fused streaming zero-fill --------
__global__ __launch_bounds__(256) void k_scores(const float* __restrict__ x,
                                                float4* __restrict__ out_zero,
                                                int zero_n4, int N) {
    int t   = blockIdx.x * blockDim.x + threadIdx.x;
    int gsz = gridDim.x * blockDim.x;

    float4 z = make_float4(0.f, 0.f, 0.f, 0.f);
    for (int i = t; i < zero_n4; i += gsz) __stcs(&out_zero[i], z);

    int lane   = threadIdx.x & 31;
    int warpId = t >> 5;
    int nWarps = gsz >> 5;

    // each lane owns 4 rows of Vi (rows lane*4 .. lane*4+3), 4 cols each
    float4 Vi[4];
    #pragma unroll
    for (int r = 0; r < 4; r++)
        Vi[r] = ((const float4*)g_Vi)[lane * 4 + r];

    const float4* x4 = (const float4*)x;
    for (int n = warpId; n < N; n += nWarps) {
        // read-once stream: evict-first so srcp/dstp (needed by later kernels)
        // stay resident in L2
        float4 xv = __ldcs(&x4[(size_t)n * 32 + lane]);
        float acc[4];
        acc[0] = xv.x * Vi[0].x + xv.y * Vi[1].x + xv.z * Vi[2].x + xv.w * Vi[3].x;
        acc[1] = xv.x * Vi[0].y + xv.y * Vi[1].y + xv.z * Vi[2].y + xv.w * Vi[3].y;
        acc[2] = xv.x * Vi[0].z + xv.y * Vi[1].z + xv.z * Vi[2].z + xv.w * Vi[3].z;
        acc[3] = xv.x * Vi[0].w + xv.y * Vi[1].w + xv.z * Vi[2].w + xv.w * Vi[3].w;
        #pragma unroll
        for (int off = 16; off > 0; off >>= 1) {
            #pragma unroll
            for (int o = 0; o < 4; o++)
                acc[o] += __shfl_xor_sync(0xFFFFFFFFu, acc[o], off);
        }
        if (lane == 0)
            ((float4*)g_si)[n] = make_float4(acc[0], acc[1], acc[2], acc[3]);
    }
}

// -------- argmax core: ONE gather (si[d]) + read-before-atomic on packed keys --------
__device__ __forceinline__ void argmax_edge(int e, int s, int d) {
    float4 si = ((const float4*)g_si)[d];
    unsigned long long k0 = make_key(si.x, (unsigned)e);
    unsigned long long k1 = make_key(si.y, (unsigned)e);
    unsigned long long k2 = make_key(si.z, (unsigned)e);
    unsigned long long k3 = make_key(si.w, (unsigned)e);
    unsigned long long* b = g_best + (size_t)s * 4;
    ulonglong2 p0 = *(const ulonglong2*)b;
    ulonglong2 p1 = *((const ulonglong2*)b + 1);
    // possibly-stale read only causes an extra (harmless) atomic
    if (k0 > p0.x) atomicMax(&b[0], k0);
    if (k1 > p0.y) atomicMax(&b[1], k1);
    if (k2 > p1.x) atomicMax(&b[2], k2);
    if (k3 > p1.y) atomicMax(&b[3], k3);
}

// -------- K3: per-edge argmax, 4 edges/thread via int4 (E % 4 == 0 path) --------
__global__ __launch_bounds__(256) void k_argmax_v4(const int* __restrict__ srcp,
                                                   const int* __restrict__ dstp, int E) {
    int e4 = (blockIdx.x * blockDim.x + threadIdx.x) * 4;
    if (e4 >= E) return;
    int4 s4 = *(const int4*)(srcp + e4);
    int4 d4 = *(const int4*)(dstp + e4);
    argmax_edge(e4 + 0, s4.x, d4.x);
    argmax_edge(e4 + 1, s4.y, d4.y);
    argmax_edge(e4 + 2, s4.z, d4.z);
    argmax_edge(e4 + 3, s4.w, d4.w);
}

__global__ __launch_bounds__(256) void k_argmax_s(const int* __restrict__ srcp,
                                                  const int* __restrict__ dstp, int E) {
    int e = blockIdx.x * blockDim.x + threadIdx.x;
    if (e >= E) return;
    argmax_edge(e, srcp[e], dstp[e]);
}

// -------- K4: winner decode, 4 best-slots (one node) per thread for MLP --------
__global__ __launch_bounds__(256) void k_winner(const int* __restrict__ dstp, int N) {
    int n = blockIdx.x * blockDim.x + threadIdx.x;   // node index
    if (n >= N) return;
    const ulonglong2* bp = (const ulonglong2*)(g_best + (size_t)n * 4);
    ulonglong2 p0 = __ldcs(bp);        // read-once
    ulonglong2 p1 = __ldcs(bp + 1);
    // issue all gathers before any store: 4 independent loads in flight
    int d0 = -1, d1 = -1, d2 = -1, d3 = -1;
    if (p0.x) d0 = dstp[0xFFFFFFFFu - (unsigned)p0.x];
    if (p0.y) d1 = dstp[0xFFFFFFFFu - (unsigned)p0.y];
    if (p1.x) d2 = dstp[0xFFFFFFFFu - (unsigned)p1.x];
    if (p1.y) d3 = dstp[0xFFFFFFFFu - (unsigned)p1.y];
    if (d0 >= 0) g_maskf[d0] = 1.0f;   // benign race: all write 1.0
    if (d1 >= 0) g_maskf[d1] = 1.0f;
    if (d2 >= 0) g_maskf[d2] = 1.0f;
    if (d3 >= 0) g_maskf[d3] = 1.0f;
}

// -------- K5: edge_keep + node_mask + slices, 4 elements/thread, streaming stores --------
__global__ __launch_bounds__(256) void k_out_v4(const int* __restrict__ srcp,
                                                const int* __restrict__ dstp,
                                                const int* __restrict__ slices,
                                                float* __restrict__ out_keep,
                                                float* __restrict__ out_mask,
                                                float* __restrict__ out_slices,
                                                int E, int N) {
    int t  = blockIdx.x * blockDim.x + threadIdx.x;
    int i4 = t * 4;
    if (i4 < E) {
        int4 s4 = *(const int4*)(srcp + i4);
        int4 d4 = *(const int4*)(dstp + i4);
        float4 r;
        r.x = g_maskf[s4.x] * g_maskf[d4.x];
        r.y = g_maskf[s4.y] * g_maskf[d4.y];
        r.z = g_maskf[s4.z] * g_maskf[d4.z];
        r.w = g_maskf[s4.w] * g_maskf[d4.w];
        __stcs((float4*)(out_keep + i4), r);        // write-once, never re-read
    }
    if (i4 < N) {
        float4 m;
        m.x = g_maskf[i4 + 0];
        m.y = (i4 + 1 < N) ? g_maskf[i4 + 1] : 0.f;
        m.z = (i4 + 2 < N) ? g_maskf[i4 + 2] : 0.f;
        m.w = (i4 + 3 < N) ? g_maskf[i4 + 3] : 0.f;
        if (i4 + 3 < N) __stcs((float4*)(out_mask + i4), m);
        else {
            out_mask[i4] = m.x;
            if (i4 + 1 < N) out_mask[i4 + 1] = m.y;
            if (i4 + 2 < N) out_mask[i4 + 2] = m.z;
        }
    }
    if (t == 0) {
        out_slices[0] = (float)slices[0];
        out_slices[1] = (float)slices[1];
    }
}

__global__ __launch_bounds__(256) void k_out_s(const int* __restrict__ srcp,
                                               const int* __restrict__ dstp,
                                               const int* __restrict__ slices,
                                               float* __restrict__ out_keep,
                                               float* __restrict__ out_mask,
                                               float* __restrict__ out_slices,
                                               int E, int N) {
    int i = blockIdx.x * blockDim.x + threadIdx.x;
    if (i < E) out_keep[i] = g_maskf[srcp[i]] * g_maskf[dstp[i]];
    if (i < N) out_mask[i] = g_maskf[i];
    if (i == 0) {
        out_slices[0] = (float)slices[0];
        out_slices[1] = (float)slices[1];
    }
}

extern "C" void kernel_launch(void* const* d_in, const int* in_sizes, int n_in,
                              void* d_out, int out_size) {
    const float* x      = (const float*)d_in[0];
    const int*   eidx   = (const int*)d_in[1];
    const int*   slices = (const int*)d_in[2];
    const float* weight = (const float*)d_in[3];
    const float* att    = (const float*)d_in[4];

    int N = in_sizes[0] / CIN;
    int E = in_sizes[1] / 2;
    const int* srcp = eidx;
    const int* dstp = eidx + E;

    float* out = (float*)d_out;
    size_t xout_elems = (size_t)N * CIN;

    if ((size_t)out_size < xout_elems + (size_t)E + (size_t)N + 2) {
        cudaMemsetAsync(out, 0, (size_t)out_size * sizeof(float), 0);
        return;
    }

    float* out_keep   = out + xout_elems;
    float* out_mask   = out_keep + E;
    float* out_slices = out_mask + N;

    int zero_n4 = (int)(xout_elems / 4);            // CIN=128 -> divisible by 4
    bool vec_ok = ((E & 3) == 0);                   // int4 alignment of dstp/out_keep

    k_init<<<(N * 4 + 255) / 256, 256>>>(weight, att, N);
    k_scores<<<1568, 256>>>(x, (float4*)out, zero_n4, N);

    if (vec_ok) k_argmax_v4<<<(E / 4 + 255) / 256, 256>>>(srcp, dstp, E);
    else        k_argmax_s<<<(E + 255) / 256, 256>>>(srcp, dstp, E);

    k_winner<<<(N + 255) / 256, 256>>>(dstp, N);

    if (vec_ok) {
        int m4 = ((E > N ? E : N) + 3) / 4;
        k_out_v4<<<(m4 + 255) / 256, 256>>>(srcp, dstp, slices, out_keep, out_mask, out_slices, E, N);
    } else {
        int m = (E > N) ? E : N;
        k_out_s<<<(m + 255) / 256, 256>>>(srcp, dstp, slices, out_keep, out_mask, out_slices, E, N);
    }
}

// round 10
// speedup vs baseline: 2.1101x; 1.0052x over previous
#include <cuda_runtime.h>
#include <cstdint>

#define NMAX   100352          // >= N = 100000
#define CIN    128

// -------- scratch (no allocations allowed) --------
// alpha(e) = s_j[src] + s_i[dst]; per-src argmax is invariant under the constant
// s_j[src] offset. Key value is s_i[dst] only -> pack dst (not edge id) in the
// low bits; tie on exact-equal si breaks by min dst (duplicate edges unaffected).
__device__ float              g_Vi[CIN * 4];       // folded weight for s_i: [k][h]
__device__ float              g_si[NMAX * 4];      // s_i[n][h]
__device__ unsigned long long g_best[NMAX * 4];    // per (src, head): (ordf(si)<<32)|(0xFFFFFFFF-dst)
__device__ float              g_maskf[NMAX];       // node_mask as float 0/1

// orderable-uint mapping for float (monotone)
__device__ __forceinline__ unsigned ordf(float f) {
    unsigned u = __float_as_uint(f);
    return (u & 0x80000000u) ? ~u : (u | 0x80000000u);
}
__device__ __forceinline__ unsigned long long make_key(float a, unsigned d) {
    return ((unsigned long long)ordf(a) << 32) | (unsigned long long)(0xFFFFFFFFu - d);
}

// -------- K1: fold weight+att into Vi (128x4) — tiny --------
__global__ __launch_bounds__(256) void k_init(const float* __restrict__ weight,
                                              const float* __restrict__ att) {
    int i = blockIdx.x * blockDim.x + threadIdx.x;
    if (i < 512) {
        int k = i >> 2;                // row of weight
        int h = i & 3;                 // head
        int base_att = h * 64 + 32;    // w_i half of att_weight
        const float* wrow = weight + k * CIN + h * 32;
        float s = 0.f;
        #pragma unroll
        for (int c = 0; c < 32; c++) s += wrow[c] * att[base_att + c];
        g_Vi[k * 4 + h] = s;
    }
}

// -------- K2: zero scratch + s_i = x @ Vi + fused streaming zero-fill of x_out --------
__global__ __launch_bounds__(256) void k_scores(const float* __restrict__ x,
                                                float4* __restrict__ out_zero,
                                                int zero_n4, int N) {
    int t   = blockIdx.x * blockDim.x + threadIdx.x;
    int gsz = gridDim.x * blockDim.x;

    // zero best table + mask (kernel boundary orders this before argmax/winner)
    for (int i = t; i < N * 4; i += gsz) g_best[i] = 0ull;
    for (int i = t; i < N;     i += gsz) g_maskf[i] = 0.0f;

    float4 z = make_float4(0.f, 0.f, 0.f, 0.f);
    for (int i = t; i < zero_n4; i += gsz) __stcs(&out_zero[i], z);

    int lane   = threadIdx.x & 31;
    int warpId = t >> 5;
    int nWarps = gsz >> 5;

    // each lane owns 4 rows of Vi (rows lane*4 .. lane*4+3), 4 cols each
    float4 Vi[4];
    #pragma unroll
    for (int r = 0; r < 4; r++)
        Vi[r] = ((const float4*)g_Vi)[lane * 4 + r];

    const float4* x4 = (const float4*)x;
    for (int n = warpId; n < N; n += nWarps) {
        // read-once stream: evict-first so srcp/dstp stay L2-resident
        float4 xv = __ldcs(&x4[(size_t)n * 32 + lane]);
        float acc[4];
        acc[0] = xv.x * Vi[0].x + xv.y * Vi[1].x + xv.z * Vi[2].x + xv.w * Vi[3].x;
        acc[1] = xv.x * Vi[0].y + xv.y * Vi[1].y + xv.z * Vi[2].y + xv.w * Vi[3].y;
        acc[2] = xv.x * Vi[0].z + xv.y * Vi[1].z + xv.z * Vi[2].z + xv.w * Vi[3].z;
        acc[3] = xv.x * Vi[0].w + xv.y * Vi[1].w + xv.z * Vi[2].w + xv.w * Vi[3].w;
        #pragma unroll
        for (int off = 16; off > 0; off >>= 1) {
            #pragma unroll
            for (int o = 0; o < 4; o++)
                acc[o] += __shfl_xor_sync(0xFFFFFFFFu, acc[o], off);
        }
        if (lane == 0)
            ((float4*)g_si)[n] = make_float4(acc[0], acc[1], acc[2], acc[3]);
    }
}

// -------- argmax core: ONE gather (si[d]) + read-before-atomic on packed keys --------
__device__ __forceinline__ void argmax_edge(int s, int d) {
    float4 si = ((const float4*)g_si)[d];
    unsigned long long k0 = make_key(si.x, (unsigned)d);
    unsigned long long k1 = make_key(si.y, (unsigned)d);
    unsigned long long k2 = make_key(si.z, (unsigned)d);
    unsigned long long k3 = make_key(si.w, (unsigned)d);
    unsigned long long* b = g_best + (size_t)s * 4;
    ulonglong2 p0 = *(const ulonglong2*)b;
    ulonglong2 p1 = *((const ulonglong2*)b + 1);
    // possibly-stale read only causes an extra (harmless) atomic
    if (k0 > p0.x) atomicMax(&b[0], k0);
    if (k1 > p0.y) atomicMax(&b[1], k1);
    if (k2 > p1.x) atomicMax(&b[2], k2);
    if (k3 > p1.y) atomicMax(&b[3], k3);
}

// -------- K3: per-edge argmax, 4 edges/thread via int4 (E % 4 == 0 path) --------
__global__ __launch_bounds__(256) void k_argmax_v4(const int* __restrict__ srcp,
                                                   const int* __restrict__ dstp, int E) {
    int e4 = (blockIdx.x * blockDim.x + threadIdx.x) * 4;
    if (e4 >= E) return;
    int4 s4 = *(const int4*)(srcp + e4);
    int4 d4 = *(const int4*)(dstp + e4);
    argmax_edge(s4.x, d4.x);
    argmax_edge(s4.y, d4.y);
    argmax_edge(s4.z, d4.z);
    argmax_edge(s4.w, d4.w);
}

__global__ __launch_bounds__(256) void k_argmax_s(const int* __restrict__ srcp,
                                                  const int* __restrict__ dstp, int E) {
    int e = blockIdx.x * blockDim.x + threadIdx.x;
    if (e >= E) return;
    argmax_edge(srcp[e], dstp[e]);
}

// -------- K4: winner decode — dst is IN the key; no gather at all --------
__global__ __launch_bounds__(256) void k_winner(int N) {
    int n = blockIdx.x * blockDim.x + threadIdx.x;   // node index
    if (n >= N) return;
    const ulonglong2* bp = (const ulonglong2*)(g_best + (size_t)n * 4);
    ulonglong2 p0 = __ldcs(bp);        // read-once, coalesced
    ulonglong2 p1 = __ldcs(bp + 1);
    // low 32 bits = 0xFFFFFFFF - dst; key==0 <=> empty segment (low bits of any
    // real key are >= 0xFFFE0000 since dst < N)
    if (p0.x) g_maskf[0xFFFFFFFFu - (unsigned)p0.x] = 1.0f;  // benign race: all write 1.0
    if (p0.y) g_maskf[0xFFFFFFFFu - (unsigned)p0.y] = 1.0f;
    if (p1.x) g_maskf[0xFFFFFFFFu - (unsigned)p1.x] = 1.0f;
    if (p1.y) g_maskf[0xFFFFFFFFu - (unsigned)p1.y] = 1.0f;
}

// -------- K5: edge_keep + node_mask + slices, 4 elements/thread, streaming stores --------
__global__ __launch_bounds__(256) void k_out_v4(const int* __restrict__ srcp,
                                                const int* __restrict__ dstp,
                                                const int* __restrict__ slices,
                                                float* __restrict__ out_keep,
                                                float* __restrict__ out_mask,
                                                float* __restrict__ out_slices,
                                                int E, int N) {
    int t  = blockIdx.x * blockDim.x + threadIdx.x;
    int i4 = t * 4;
    if (i4 < E) {
        int4 s4 = *(const int4*)(srcp + i4);
        int4 d4 = *(const int4*)(dstp + i4);
        float4 r;
        r.x = g_maskf[s4.x] * g_maskf[d4.x];
        r.y = g_maskf[s4.y] * g_maskf[d4.y];
        r.z = g_maskf[s4.z] * g_maskf[d4.z];
        r.w = g_maskf[s4.w] * g_maskf[d4.w];
        __stcs((float4*)(out_keep + i4), r);        // write-once, never re-read
    }
    if (i4 < N) {
        float4 m;
        m.x = g_maskf[i4 + 0];
        m.y = (i4 + 1 < N) ? g_maskf[i4 + 1] : 0.f;
        m.z = (i4 + 2 < N) ? g_maskf[i4 + 2] : 0.f;
        m.w = (i4 + 3 < N) ? g_maskf[i4 + 3] : 0.f;
        if (i4 + 3 < N) __stcs((float4*)(out_mask + i4), m);
        else {
            out_mask[i4] = m.x;
            if (i4 + 1 < N) out_mask[i4 + 1] = m.y;
            if (i4 + 2 < N) out_mask[i4 + 2] = m.z;
        }
    }
    if (t == 0) {
        out_slices[0] = (float)slices[0];
        out_slices[1] = (float)slices[1];
    }
}

__global__ __launch_bounds__(256) void k_out_s(const int* __restrict__ srcp,
                                               const int* __restrict__ dstp,
                                               const int* __restrict__ slices,
                                               float* __restrict__ out_keep,
                                               float* __restrict__ out_mask,
                                               float* __restrict__ out_slices,
                                               int E, int N) {
    int i = blockIdx.x * blockDim.x + threadIdx.x;
    if (i < E) out_keep[i] = g_maskf[srcp[i]] * g_maskf[dstp[i]];
    if (i < N) out_mask[i] = g_maskf[i];
    if (i == 0) {
        out_slices[0] = (float)slices[0];
        out_slices[1] = (float)slices[1];
    }
}

extern "C" void kernel_launch(void* const* d_in, const int* in_sizes, int n_in,
                              void* d_out, int out_size) {
    const float* x      = (const float*)d_in[0];
    const int*   eidx   = (const int*)d_in[1];
    const int*   slices = (const int*)d_in[2];
    const float* weight = (const float*)d_in[3];
    const float* att    = (const float*)d_in[4];

    int N = in_sizes[0] / CIN;
    int E = in_sizes[1] / 2;
    const int* srcp = eidx;
    const int* dstp = eidx + E;

    float* out = (float*)d_out;
    size_t xout_elems = (size_t)N * CIN;

    if ((size_t)out_size < xout_elems + (size_t)E + (size_t)N + 2) {
        cudaMemsetAsync(out, 0, (size_t)out_size * sizeof(float), 0);
        return;
    }

    float* out_keep   = out + xout_elems;
    float* out_mask   = out_keep + E;
    float* out_slices = out_mask + N;

    int zero_n4 = (int)(xout_elems / 4);            // CIN=128 -> divisible by 4
    bool vec_ok = ((E & 3) == 0);                   // int4 alignment of dstp/out_keep

    k_init<<<2, 256>>>(weight, att);
    k_scores<<<1568, 256>>>(x, (float4*)out, zero_n4, N);

    if (vec_ok) k_argmax_v4<<<(E / 4 + 255) / 256, 256>>>(srcp, dstp, E);
    else        k_argmax_s<<<(E + 255) / 256, 256>>>(srcp, dstp, E);

    k_winner<<<(N + 255) / 256, 256>>>(N);

    if (vec_ok) {
        int m4 = ((E > N ? E : N) + 3) / 4;
        k_out_v4<<<(m4 + 255) / 256, 256>>>(srcp, dstp, slices, out_keep, out_mask, out_slices, E, N);
    } else {
        int m = (E > N) ? E : N;
        k_out_s<<<(m + 255) / 256, 256>>>(srcp, dstp, slices, out_keep, out_mask, out_slices, E, N);
    }
}